// round 11
// baseline (speedup 1.0000x reference)
#include <cuda_runtime.h>
#include <math.h>

#define TILE_B   32
#define NTHREADS 512
#define NCHUNK   16
#define NPIX     784
#define NCLS     10
#define PPC      49        // pixels per chunk (784 / 16)
#define TP       8         // staging tile pixels
#define NTILE    6         // 6*8 = 48, +1 leftover pixel

// smem layout (dynamic, floats):
//   wbuf [784][12]   : per-pixel class weights (10 used + 2 pad), 48B rows (37632 B)
//   zab  [784][2]    : per-pixel (alpha_q, beta_q)                       ( 6272 B)
//   xstg [16][8][36] : per-warp staging, pad-36 (conflict-free)          (18432 B)
// after main loop, wbuf region is reused for part[16][32][10] + red[32][10]
#define WBUF_F (NPIX * 12)              // 9408
#define ZAB_F  (NPIX * 2)               // 1568
#define XSTG_F (NCHUNK * TP * 36)       // 4608
#define SMEM_BYTES ((WBUF_F + ZAB_F + XSTG_F) * 4)   // 62336

__device__ __forceinline__ unsigned long long pack2(float lo, float hi) {
    unsigned long long r;
    asm("mov.b64 %0, {%1, %2};" : "=l"(r) : "f"(lo), "f"(hi));
    return r;
}
__device__ __forceinline__ unsigned long long ffma2(unsigned long long a,
                                                    unsigned long long b,
                                                    unsigned long long c) {
    unsigned long long d;
    asm("fma.rn.f32x2 %0, %1, %2, %3;" : "=l"(d) : "l"(a), "l"(b), "l"(c));
    return d;
}
__device__ __forceinline__ float2 unpack2(unsigned long long v) {
    float lo, hi;
    asm("mov.b64 {%0, %1}, %2;" : "=f"(lo), "=f"(hi) : "l"(v));
    return make_float2(lo, hi);
}

__global__ __launch_bounds__(NTHREADS, 2)
void quanv_fused_kernel(const float* __restrict__ x,
                        const float* __restrict__ params,
                        const float* __restrict__ w,
                        const float* __restrict__ bias,
                        float* __restrict__ out,
                        int B, int depth)
{
    extern __shared__ float sm[];
    float* wbuf = sm;                       // [784][12]
    float* zab  = sm + WBUF_F;              // [784][2]
    float* xstg = sm + WBUF_F + ZAB_F;      // [16][8][36]
    __shared__ float ab[8];                 // ab[q]=beta_q (cos), ab[4+q]=alpha_q (sin)

    const int tid   = threadIdx.x;
    const int lane  = tid & 31;
    const int chunk = tid >> 5;

    // ---- Phase 0: alpha/beta per qubit via exact 2x2 complex simulation ----
    if (tid < 8) {
        const int q     = tid & 3;
        const int which = tid >> 2;
        float ar = which ? 0.70710678118654752f : 1.0f, ai = 0.0f;
        float br = which ? 0.70710678118654752f : 0.0f, bi = 0.0f;
        for (int d = 0; d < depth; d++) {
            const float rz1 = params[d * 12 + q * 3 + 0];
            const float ry  = params[d * 12 + q * 3 + 1];
            const float rz2 = params[d * 12 + q * 3 + 2];
            float p1i, p1r; __sincosf(0.5f * rz1, &p1i, &p1r); p1i = -p1i;
            float nar = ar * p1r - ai * p1i, nai = ar * p1i + ai * p1r;
            float nbr = br * p1r + bi * p1i, nbi = bi * p1r - br * p1i;
            ar = nar; ai = nai; br = nbr; bi = nbi;
            float s, c; __sincosf(0.5f * ry, &s, &c);
            nar = c * ar - s * br; nai = c * ai - s * bi;
            nbr = s * ar + c * br; nbi = s * ai + c * bi;
            ar = nar; ai = nai; br = nbr; bi = nbi;
            float p2i, p2r; __sincosf(0.5f * rz2, &p2i, &p2r); p2i = -p2i;
            nar = ar * p2r - ai * p2i; nai = ar * p2i + ai * p2r;
            nbr = br * p2r + bi * p2i; nbi = bi * p2r - br * p2i;
            ar = nar; ai = nai; br = nbr; bi = nbi;
        }
        ab[which * 4 + q] = (ar * ar + ai * ai) - (br * br + bi * bi);
    }
    __syncthreads();

    // ---- Phase 1: permute w into pixel-order (NO alpha/beta fold) + zab ----
    for (int idx = tid; idx < NPIX * NCLS; idx += NTHREADS) {
        const int pix = idx / NCLS;
        const int c   = idx - pix * NCLS;
        const int r   = pix / 28;
        const int cc  = pix - r * 28;
        const int q   = ((r & 1) << 1) + (cc & 1);
        const int f   = (((r >> 1) * 14 + (cc >> 1)) << 2) + q;
        wbuf[pix * 12 + c] = w[c * NPIX + f];
    }
    for (int pix = tid; pix < NPIX; pix += NTHREADS) {
        const int r  = pix / 28;
        const int q  = ((r & 1) << 1) + (pix & 1);   // (pix%28)&1 == pix&1 (28 even)
        zab[pix * 2 + 0] = ab[4 + q];   // alpha (sin coeff)
        zab[pix * 2 + 1] = ab[q];       // beta  (cos coeff)
    }
    __syncthreads();

    // ---- Phase 2: main accumulation ----
    // warp = 32 images, chunk = 49 pixels. Per image-pixel: one scalar feature
    // z = alpha*sin(x) + beta*cos(x), then 5 packed FFMA2 against 10 weights.
    const int b0   = blockIdx.x * TILE_B;
    const int bmax = B - 1 - b0;
    const int p0   = chunk * PPC;
    float* xsw = xstg + chunk * (TP * 36);

    const int sp = lane & 7;    // staging pixel within tile
    const int si = lane >> 3;   // staging image group offset

    unsigned long long acc[5];
#pragma unroll
    for (int j = 0; j < 5; j++) acc[j] = 0ull;

    for (int t = 0; t < NTILE; t++) {
        const int tb = p0 + t * TP;
#pragma unroll
        for (int pass = 0; pass < 8; pass++) {
            int img = si + pass * 4;
            int ri = (img <= bmax) ? img : (bmax < 0 ? 0 : bmax);
            xsw[sp * 36 + img] = x[(size_t)(b0 + ri) * NPIX + tb + sp];
        }
        __syncwarp();
#pragma unroll 2
        for (int k = 0; k < TP; k++) {
            const float xv = xsw[k * 36 + lane];
            float s, co;
            __sincosf(xv, &s, &co);
            const float2 zz = *reinterpret_cast<const float2*>(zab + (tb + k) * 2);
            const float z = fmaf(s, zz.x, co * zz.y);
            const unsigned long long zp = pack2(z, z);
            const float* wrow = wbuf + (tb + k) * 12;
            const ulonglong2 v01 = *reinterpret_cast<const ulonglong2*>(wrow);
            const ulonglong2 v23 = *reinterpret_cast<const ulonglong2*>(wrow + 4);
            const unsigned long long v4 = *reinterpret_cast<const unsigned long long*>(wrow + 8);
            acc[0] = ffma2(v01.x, zp, acc[0]);
            acc[1] = ffma2(v01.y, zp, acc[1]);
            acc[2] = ffma2(v23.x, zp, acc[2]);
            acc[3] = ffma2(v23.y, zp, acc[3]);
            acc[4] = ffma2(v4,    zp, acc[4]);
        }
        __syncwarp();
    }
    // leftover pixel (49 = 6*8 + 1): direct per-lane load
    {
        const int pix = p0 + 48;
        const int ri = (lane <= bmax) ? lane : (bmax < 0 ? 0 : bmax);
        const float xv = x[(size_t)(b0 + ri) * NPIX + pix];
        float s, co;
        __sincosf(xv, &s, &co);
        const float2 zz = *reinterpret_cast<const float2*>(zab + pix * 2);
        const float z = fmaf(s, zz.x, co * zz.y);
        const unsigned long long zp = pack2(z, z);
        const float* wrow = wbuf + pix * 12;
        const ulonglong2 v01 = *reinterpret_cast<const ulonglong2*>(wrow);
        const ulonglong2 v23 = *reinterpret_cast<const ulonglong2*>(wrow + 4);
        const unsigned long long v4 = *reinterpret_cast<const unsigned long long*>(wrow + 8);
        acc[0] = ffma2(v01.x, zp, acc[0]);
        acc[1] = ffma2(v01.y, zp, acc[1]);
        acc[2] = ffma2(v23.x, zp, acc[2]);
        acc[3] = ffma2(v23.y, zp, acc[3]);
        acc[4] = ffma2(v4,    zp, acc[4]);
    }

    // ---- Phase 3: cross-chunk reduce + log-softmax (wbuf region reused) ----
    __syncthreads();                       // all warps done reading wbuf/zab
    float* part = sm;                      // [16][32][10]
    float* red  = sm + NCHUNK * TILE_B * NCLS;  // [32][10]
    float* my = part + (chunk * TILE_B + lane) * NCLS;
#pragma unroll
    for (int j = 0; j < 5; j++) {
        const float2 f2 = unpack2(acc[j]);   // (class 2j, class 2j+1)
        my[2 * j]     = f2.x;
        my[2 * j + 1] = f2.y;
    }
    __syncthreads();

    if (tid < TILE_B * NCLS) {             // 320 threads: one (img, class) each
        const int img = tid / NCLS;
        const int c   = tid - img * NCLS;
        float sum = bias[c];
#pragma unroll
        for (int ch = 0; ch < NCHUNK; ch++)
            sum += part[(ch * TILE_B + img) * NCLS + c];
        red[img * NCLS + c] = sum;
    }
    __syncthreads();

    if (tid < TILE_B) {
        const int b2 = b0 + tid;
        if (b2 < B) {
            float l[NCLS];
#pragma unroll
            for (int c = 0; c < NCLS; c++) l[c] = red[tid * NCLS + c];
            float m = l[0];
#pragma unroll
            for (int c = 1; c < NCLS; c++) m = fmaxf(m, l[c]);
            float se = 0.0f;
#pragma unroll
            for (int c = 0; c < NCLS; c++) se += expf(l[c] - m);
            const float lse = m + logf(se);
            float* orow = out + (size_t)b2 * NCLS;
#pragma unroll
            for (int c = 0; c < NCLS; c++) orow[c] = l[c] - lse;
        }
    }
}

extern "C" void kernel_launch(void* const* d_in, const int* in_sizes, int n_in,
                              void* d_out, int out_size)
{
    const float* x      = (const float*)d_in[0];
    const float* params = (const float*)d_in[1];
    const float* w      = (const float*)d_in[2];
    const float* bias   = (const float*)d_in[3];
    float* out          = (float*)d_out;

    const int B     = in_sizes[0] / NPIX;
    const int depth = in_sizes[1] / 12;

    cudaFuncSetAttribute(quanv_fused_kernel,
                         cudaFuncAttributeMaxDynamicSharedMemorySize, SMEM_BYTES);

    const int grid = (B + TILE_B - 1) / TILE_B;
    quanv_fused_kernel<<<grid, NTHREADS, SMEM_BYTES>>>(x, params, w, bias, out, B, depth);
}

// round 16
// speedup vs baseline: 1.1398x; 1.1398x over previous
#include <cuda_runtime.h>
#include <math.h>

#define TILE_B   32
#define NTHREADS 512
#define NCHUNK   16
#define NPIX     784
#define NCLS     10
#define TP       8         // staging tile pixels
#define NTILE    6         // 6*8 = 48 px per chunk; +1 leftover pixel (768+chunk)
#define XS       10        // staging stride (img-major): 8 px + 2 pad

// smem (dynamic, floats):
//   wbuf [784][12] : per-pixel [w0..w9, alpha, beta], 48B rows        (37632 B)
//   xstg [16][32][10] : per-warp img-major staging                    (20480 B)
// after main loop the whole region is reused for part[32][32][10] + red[32][10]
#define WBUF_F (NPIX * 12)              // 9408
#define XSTG_F (NCHUNK * TILE_B * XS)   // 5120
#define SMEM_BYTES ((WBUF_F + XSTG_F) * 4)   // 58112

__device__ __forceinline__ unsigned long long pack2(float lo, float hi) {
    unsigned long long r;
    asm("mov.b64 %0, {%1, %2};" : "=l"(r) : "f"(lo), "f"(hi));
    return r;
}
__device__ __forceinline__ unsigned long long ffma2(unsigned long long a,
                                                    unsigned long long b,
                                                    unsigned long long c) {
    unsigned long long d;
    asm("fma.rn.f32x2 %0, %1, %2, %3;" : "=l"(d) : "l"(a), "l"(b), "l"(c));
    return d;
}
__device__ __forceinline__ float2 unpack2(unsigned long long v) {
    float lo, hi;
    asm("mov.b64 {%0, %1}, %2;" : "=f"(lo), "=f"(hi) : "l"(v));
    return make_float2(lo, hi);
}

__global__ __launch_bounds__(NTHREADS, 2)
void quanv_fused_kernel(const float* __restrict__ x,
                        const float* __restrict__ params,
                        const float* __restrict__ w,
                        const float* __restrict__ bias,
                        float* __restrict__ out,
                        int B, int depth)
{
    extern __shared__ float sm[];
    float* wbuf = sm;                       // [784][12]
    float* xstg = sm + WBUF_F;              // [16][32][10]
    __shared__ float ab[8];                 // ab[q]=beta_q, ab[4+q]=alpha_q

    const int tid   = threadIdx.x;
    const int lane  = tid & 31;
    const int chunk = tid >> 5;
    const int hl    = lane >> 4;            // pixel parity handled by this lane
    const int il    = lane & 15;            // image index (also il+16)

    // ---- Phase 0: alpha/beta per qubit via exact 2x2 complex simulation ----
    if (tid < 8) {
        const int q     = tid & 3;
        const int which = tid >> 2;
        float ar = which ? 0.70710678118654752f : 1.0f, ai = 0.0f;
        float br = which ? 0.70710678118654752f : 0.0f, bi = 0.0f;
        for (int d = 0; d < depth; d++) {
            const float rz1 = params[d * 12 + q * 3 + 0];
            const float ry  = params[d * 12 + q * 3 + 1];
            const float rz2 = params[d * 12 + q * 3 + 2];
            float p1i, p1r; __sincosf(0.5f * rz1, &p1i, &p1r); p1i = -p1i;
            float nar = ar * p1r - ai * p1i, nai = ar * p1i + ai * p1r;
            float nbr = br * p1r + bi * p1i, nbi = bi * p1r - br * p1i;
            ar = nar; ai = nai; br = nbr; bi = nbi;
            float s, c; __sincosf(0.5f * ry, &s, &c);
            nar = c * ar - s * br; nai = c * ai - s * bi;
            nbr = s * ar + c * br; nbi = s * ai + c * bi;
            ar = nar; ai = nai; br = nbr; bi = nbi;
            float p2i, p2r; __sincosf(0.5f * rz2, &p2i, &p2r); p2i = -p2i;
            nar = ar * p2r - ai * p2i; nai = ar * p2i + ai * p2r;
            nbr = br * p2r + bi * p2i; nbi = bi * p2r - br * p2i;
            ar = nar; ai = nai; br = nbr; bi = nbi;
        }
        ab[which * 4 + q] = (ar * ar + ai * ai) - (br * br + bi * bi);
    }
    __syncthreads();

    // ---- Phase 1: build wbuf rows [w0..w9, alpha_q, beta_q] in pixel order ----
    for (int idx = tid; idx < NPIX * 12; idx += NTHREADS) {
        const int pix = idx / 12;
        const int c   = idx - pix * 12;
        const int r   = pix / 28;
        const int cc  = pix - r * 28;
        const int q   = ((r & 1) << 1) + (cc & 1);
        float val;
        if (c < NCLS) {
            const int f = (((r >> 1) * 14 + (cc >> 1)) << 2) + q;
            val = w[c * NPIX + f];
        } else if (c == 10) {
            val = ab[4 + q];          // alpha (sin coeff)
        } else {
            val = ab[q];              // beta (cos coeff)
        }
        wbuf[idx] = val;
    }
    __syncthreads();

    // ---- Phase 2: main accumulation ----
    // chunk c owns pixels [48c, 48c+48) plus leftover pixel 768+c.
    // 48c is even -> every tile base tb is even -> float2 global loads 8B-aligned.
    // Half-warp pixel pairing: lanes 0-15 do pixel k, lanes 16-31 pixel k+1;
    // each lane owns images il and il+16.
    const int b0   = blockIdx.x * TILE_B;
    const int bmax = B - 1 - b0;
    const int p0   = chunk * 48;
    float* xsw = xstg + chunk * (TILE_B * XS);

    const int spp = lane & 3;    // staging pixel-pair (px 2spp, 2spp+1)
    const int sig = lane >> 2;   // staging image group (img = sig + 8*pass)

    unsigned long long acc0[5], acc1[5];
#pragma unroll
    for (int j = 0; j < 5; j++) { acc0[j] = 0ull; acc1[j] = 0ull; }

    for (int t = 0; t < NTILE; t++) {
        const int tb = p0 + t * TP;
        // stage: LDG.64 (2 px, 1 img) -> STS.64, img-major stride 10
#pragma unroll
        for (int pass = 0; pass < 4; pass++) {
            int img = sig + pass * 8;
            int ri = (img <= bmax) ? img : (bmax < 0 ? 0 : bmax);
            const float2 v = *reinterpret_cast<const float2*>(
                x + (size_t)(b0 + ri) * NPIX + tb + 2 * spp);
            *reinterpret_cast<float2*>(xsw + img * XS + 2 * spp) = v;
        }
        __syncwarp();
#pragma unroll
        for (int k = 0; k < TP; k += 2) {
            const int kp = k + hl;                  // this lane's pixel in tile
            const float xv0 = xsw[il * XS + kp];
            const float xv1 = xsw[(il + 16) * XS + kp];
            const float* wrow = wbuf + (tb + kp) * 12;
            const ulonglong2 vA = *reinterpret_cast<const ulonglong2*>(wrow);
            const ulonglong2 vB = *reinterpret_cast<const ulonglong2*>(wrow + 4);
            const ulonglong2 vC = *reinterpret_cast<const ulonglong2*>(wrow + 8);
            const float2 al_be = unpack2(vC.y);     // (alpha, beta)
            float s0, c0, s1, c1;
            __sincosf(xv0, &s0, &c0);
            __sincosf(xv1, &s1, &c1);
            const float z0 = fmaf(s0, al_be.x, c0 * al_be.y);
            const float z1 = fmaf(s1, al_be.x, c1 * al_be.y);
            const unsigned long long zp0 = pack2(z0, z0);
            const unsigned long long zp1 = pack2(z1, z1);
            acc0[0] = ffma2(vA.x, zp0, acc0[0]);  acc1[0] = ffma2(vA.x, zp1, acc1[0]);
            acc0[1] = ffma2(vA.y, zp0, acc0[1]);  acc1[1] = ffma2(vA.y, zp1, acc1[1]);
            acc0[2] = ffma2(vB.x, zp0, acc0[2]);  acc1[2] = ffma2(vB.x, zp1, acc1[2]);
            acc0[3] = ffma2(vB.y, zp0, acc0[3]);  acc1[3] = ffma2(vB.y, zp1, acc1[3]);
            acc0[4] = ffma2(vC.x, zp0, acc0[4]);  acc1[4] = ffma2(vC.x, zp1, acc1[4]);
        }
        __syncwarp();
    }
    // leftover pixel 768 + chunk: lanes 0-15 only (they cover all 32 images)
    if (hl == 0) {
        const int pix = 768 + chunk;
        const int r0i = (il <= bmax) ? il : (bmax < 0 ? 0 : bmax);
        const int r1i = (il + 16 <= bmax) ? il + 16 : (bmax < 0 ? 0 : bmax);
        const float xv0 = x[(size_t)(b0 + r0i) * NPIX + pix];
        const float xv1 = x[(size_t)(b0 + r1i) * NPIX + pix];
        const float* wrow = wbuf + pix * 12;
        const ulonglong2 vA = *reinterpret_cast<const ulonglong2*>(wrow);
        const ulonglong2 vB = *reinterpret_cast<const ulonglong2*>(wrow + 4);
        const ulonglong2 vC = *reinterpret_cast<const ulonglong2*>(wrow + 8);
        const float2 al_be = unpack2(vC.y);
        float s0, c0, s1, c1;
        __sincosf(xv0, &s0, &c0);
        __sincosf(xv1, &s1, &c1);
        const float z0 = fmaf(s0, al_be.x, c0 * al_be.y);
        const float z1 = fmaf(s1, al_be.x, c1 * al_be.y);
        const unsigned long long zp0 = pack2(z0, z0);
        const unsigned long long zp1 = pack2(z1, z1);
        acc0[0] = ffma2(vA.x, zp0, acc0[0]);  acc1[0] = ffma2(vA.x, zp1, acc1[0]);
        acc0[1] = ffma2(vA.y, zp0, acc0[1]);  acc1[1] = ffma2(vA.y, zp1, acc1[1]);
        acc0[2] = ffma2(vB.x, zp0, acc0[2]);  acc1[2] = ffma2(vB.x, zp1, acc1[2]);
        acc0[3] = ffma2(vB.y, zp0, acc0[3]);  acc1[3] = ffma2(vB.y, zp1, acc1[3]);
        acc0[4] = ffma2(vC.x, zp0, acc0[4]);  acc1[4] = ffma2(vC.x, zp1, acc1[4]);
    }

    // ---- Phase 3: cross-group reduce + log-softmax (smem reused) ----
    __syncthreads();                            // all warps done with wbuf/xstg
    float* part = sm;                           // [32 groups][32 img][10]
    float* red  = sm + 32 * TILE_B * NCLS;      // [32][10]
    const int grp = (chunk << 1) + hl;
    float* r0 = part + (grp * TILE_B + il) * NCLS;
    float* r1 = part + (grp * TILE_B + il + 16) * NCLS;
#pragma unroll
    for (int j = 0; j < 5; j++) {
        const float2 f0 = unpack2(acc0[j]);
        const float2 f1 = unpack2(acc1[j]);
        r0[2 * j] = f0.x;  r0[2 * j + 1] = f0.y;
        r1[2 * j] = f1.x;  r1[2 * j + 1] = f1.y;
    }
    __syncthreads();

    if (tid < TILE_B * NCLS) {                 // 320 threads: one (img, class)
        const int img = tid / NCLS;
        const int c   = tid - img * NCLS;
        float sum = bias[c];
#pragma unroll
        for (int g = 0; g < 32; g++)
            sum += part[(g * TILE_B + img) * NCLS + c];
        red[img * NCLS + c] = sum;
    }
    __syncthreads();

    if (tid < TILE_B) {
        const int b2 = b0 + tid;
        if (b2 < B) {
            float l[NCLS];
#pragma unroll
            for (int c = 0; c < NCLS; c++) l[c] = red[tid * NCLS + c];
            float m = l[0];
#pragma unroll
            for (int c = 1; c < NCLS; c++) m = fmaxf(m, l[c]);
            float se = 0.0f;
#pragma unroll
            for (int c = 0; c < NCLS; c++) se += expf(l[c] - m);
            const float lse = m + logf(se);
            float* orow = out + (size_t)b2 * NCLS;
#pragma unroll
            for (int c = 0; c < NCLS; c++) orow[c] = l[c] - lse;
        }
    }
}

extern "C" void kernel_launch(void* const* d_in, const int* in_sizes, int n_in,
                              void* d_out, int out_size)
{
    const float* x      = (const float*)d_in[0];
    const float* params = (const float*)d_in[1];
    const float* w      = (const float*)d_in[2];
    const float* bias   = (const float*)d_in[3];
    float* out          = (float*)d_out;

    const int B     = in_sizes[0] / NPIX;
    const int depth = in_sizes[1] / 12;

    cudaFuncSetAttribute(quanv_fused_kernel,
                         cudaFuncAttributeMaxDynamicSharedMemorySize, SMEM_BYTES);

    const int grid = (B + TILE_B - 1) / TILE_B;
    quanv_fused_kernel<<<grid, NTHREADS, SMEM_BYTES>>>(x, params, w, bias, out, B, depth);
}